// round 15
// baseline (speedup 1.0000x reference)
#include <cuda_runtime.h>
#include <stdint.h>

#define Bn 16384
#define Tn 256
#define Dn 8
#define Fn 512
#define Cn 16
#define Ln 256

#define NBLK 148             // persistent accum blocks, 1 per SM
#define NSLOT (2 * NBLK)     // <=2 partial segments per block

// u0(i) = 1024*i/37  (== 4096*i/148, exact at i=148)
#define U0(i) ((1024 * (i)) / 37)

// ---------------- device scratch (static, no runtime allocation) ------------
__device__ unsigned short g_fidx16[Tn * Dn];   // PRE-SCALED byte offsets
__device__ unsigned char  g_dec[(size_t)Tn * Bn];             // 4 MB [T][B]
__device__ float          g_part[(size_t)NSLOT * 1024 * Cn];  // 19.4 MB partials
__device__ int            g_scratch[16];

// ---------------- kernel 1: argmax over F per (tree, depth) -----------------
__global__ void k_argmax(const float* __restrict__ fw) {
    int g    = blockIdx.x * 8 + (threadIdx.x >> 5);   // 2048 warps total
    int lane = threadIdx.x & 31;
    const float* p = fw + (size_t)g * Fn;

    float v[16];
    #pragma unroll
    for (int i = 0; i < 16; i++) v[i] = p[lane + (i << 5)];

    float best = v[0];
    int   bi   = lane;
    #pragma unroll
    for (int i = 1; i < 16; i++)
        if (v[i] > best) { best = v[i]; bi = lane + (i << 5); }

    #pragma unroll
    for (int off = 16; off; off >>= 1) {
        float ov = __shfl_down_sync(0xffffffffu, best, off);
        int   oi = __shfl_down_sync(0xffffffffu, bi,   off);
        if (ov > best || (ov == best && oi < bi)) { best = ov; bi = oi; }
    }
    if (lane == 0)
        g_fidx16[g] = (unsigned short)((((bi & 3) << 7) + (bi >> 2)) << 2);
}

// ---------------- kernel 2: per-(sample,tree) decision byte -----------------
// (round-13 version — best measured; LSU-floor-bound, closed)
__global__ __launch_bounds__(512) void k_decide(const float* __restrict__ x,
                                                const float* __restrict__ thr) {
    extern __shared__ float smem[];
    float* s_x   = smem;                                   // 32 * 513 floats
    uint4* s_fpk = (uint4*)(smem + 32 * 513);              // 256 * 16 B
    float* s_thr = (float*)(s_fpk + Tn);                   // 2048 floats

    int tid = threadIdx.x;
    int b0  = blockIdx.x * 32;

    const float4* xg = (const float4*)x + (size_t)b0 * (Fn / 4);
    for (int i = tid; i < 32 * (Fn / 4); i += 512) {
        float4 v = xg[i];
        int row = i >> 7, c4 = i & 127;
        float* dst = s_x + row * 513 + c4;
        dst[0]   = v.x;
        dst[128] = v.y;
        dst[256] = v.z;
        dst[384] = v.w;
    }
    for (int i = tid; i < (Tn * Dn) / 2; i += 512)
        ((unsigned*)s_fpk)[i] = ((const unsigned*)g_fidx16)[i];
    for (int i = tid; i < Tn * Dn; i += 512)
        s_thr[i] = thr[i];
    __syncthreads();

    int warp = tid >> 5, lane = tid & 31;
    const char* xr = (const char*)(s_x + lane * 513);

    #pragma unroll 4
    for (int tt = 0; tt < 16; tt++) {
        int t = warp * 16 + tt;
        uint4 fp = s_fpk[t];
        const float4* th = (const float4*)(s_thr + t * 8);
        float4 t0 = th[0], t1 = th[1];
        float x0 = *(const float*)(xr + (fp.x & 0xFFFFu));
        float x1 = *(const float*)(xr + (fp.x >> 16));
        float x2 = *(const float*)(xr + (fp.y & 0xFFFFu));
        float x3 = *(const float*)(xr + (fp.y >> 16));
        float x4 = *(const float*)(xr + (fp.z & 0xFFFFu));
        float x5 = *(const float*)(xr + (fp.z >> 16));
        float x6 = *(const float*)(xr + (fp.w & 0xFFFFu));
        float x7 = *(const float*)(xr + (fp.w >> 16));
        unsigned s0 = __float_as_uint(t0.x - x0) >> 31;
        unsigned s1 = __float_as_uint(t0.y - x1) >> 31;
        unsigned s2 = __float_as_uint(t0.z - x2) >> 31;
        unsigned s3 = __float_as_uint(t0.w - x3) >> 31;
        unsigned s4 = __float_as_uint(t1.x - x4) >> 31;
        unsigned s5 = __float_as_uint(t1.y - x5) >> 31;
        unsigned s6 = __float_as_uint(t1.z - x6) >> 31;
        unsigned s7 = __float_as_uint(t1.w - x7) >> 31;
        unsigned dec = (s0 << 7) | (s1 << 6) | (s2 << 5) | (s3 << 4) |
                       (s4 << 3) | (s5 << 2) | (s6 << 1) | s7;
        g_dec[(size_t)t * Bn + b0 + lane] = (unsigned char)dec;
    }
}

// ---------------- launch-slot shim (keeps k_accum in the ncu slot) ----------
__global__ void k_tiny() { if (threadIdx.x < 16) g_scratch[threadIdx.x] = 0; }

// ---------------- kernel 3: persistent gather, GROUP-OF-4 tree staging -------
// 148 blocks x 1024 threads (1/SM). smem: two 64 KB buffers of 4 swizzled
// trees each + dec table (156 KB total, fine at 1 block/SM). Per group:
// 4 dec LDS + 16 gathers per thread with NO barrier in between -> 4x fewer
// barriers than round 14 and longer independent LDS bursts; staging is 4-wide
// LDG prefetch (full MLP) + 4 STS per thread.
__global__ __launch_bounds__(1024) void k_accum(const float* __restrict__ resp) {
    extern __shared__ float4 dynsmem[];
    float4*   s_r    = dynsmem;                        // 2 * 4096 float4 = 128 KB
    unsigned* s_dall = (unsigned*)(dynsmem + 8192);    // up to 28*256 u32 (28 KB)

    int i   = blockIdx.x;
    int tid = threadIdx.x;
    int w   = tid >> 5;
    int l   = tid & 31;
    int q   = l & 3;
    int sg  = l >> 2;
    int sbase = w * 32 + sg * 4;           // first of this thread's 4 samples
    int dword = sbase >> 2;                // dec word index for this thread

    // swizzled STS slot for this thread's staging element
    int dst_d = tid >> 2, dst_k = tid & 3;
    int swst  = dst_d * 4 + ((dst_k + (dst_d >> 1)) & 3);

    int ustart = U0(i), uend = U0(i + 1);
    int ph = 0;

    for (int u = ustart; u < uend; ) {
        int bt     = u >> 8;
        int segend = min(uend, (bt + 1) << 8);
        int nt     = segend - u;           // 1..28 trees this segment
        int t0     = u - (bt << 8);        // first (global) tree index
        int b0     = bt << 10;             // first sample of this btile
        int ngr    = (nt + 3) >> 2;        // groups of 4 trees

        // stage ALL dec words for this segment
        for (int j = tid; j < nt * 256; j += 1024) {
            int tt = j >> 8, wd = j & 255;
            s_dall[j] =
                *((const unsigned*)(g_dec + (size_t)(t0 + tt) * Bn + b0) + wd);
        }

        float4 a0 = make_float4(0.f, 0.f, 0.f, 0.f);
        float4 a1 = a0, a2 = a0, a3 = a0;
        float4 nv0, nv1, nv2, nv3;

        // stage group 0 directly into buf0
        {
            int gs = min(4, nt);
            const float4* rs = (const float4*)resp + (size_t)t0 * 1024 + tid;
            if (0 < gs) s_r[0 * 1024 + swst] = rs[0];
            if (1 < gs) s_r[1 * 1024 + swst] = rs[1024];
            if (2 < gs) s_r[2 * 1024 + swst] = rs[2048];
            if (3 < gs) s_r[3 * 1024 + swst] = rs[3072];
        }
        // prefetch group 1 into nv
        if (ngr > 1) {
            int gs = min(4, nt - 4);
            const float4* rs = (const float4*)resp + (size_t)(t0 + 4) * 1024 + tid;
            if (0 < gs) nv0 = rs[0];
            if (1 < gs) nv1 = rs[1024];
            if (2 < gs) nv2 = rs[2048];
            if (3 < gs) nv3 = rs[3072];
        }
        __syncthreads();

        for (int g = 0; g < ngr; g++) {
            int gbase = g << 2;
            int gs    = min(4, nt - gbase);
            const float4* bufp = s_r + (size_t)(g & 1) * 4096;

            #pragma unroll
            for (int j = 0; j < 4; j++) {
                if (j < gs) {
                    unsigned dw = s_dall[(gbase + j) * 256 + dword];
                    const float4* sr = bufp + j * 1024;
                    int d0 = dw & 255, d1 = (dw >> 8) & 255;
                    int d2 = (dw >> 16) & 255, d3 = dw >> 24;
                    float4 v0 = sr[d0 * 4 + ((q + (d0 >> 1)) & 3)];
                    float4 v1 = sr[d1 * 4 + ((q + (d1 >> 1)) & 3)];
                    float4 v2 = sr[d2 * 4 + ((q + (d2 >> 1)) & 3)];
                    float4 v3 = sr[d3 * 4 + ((q + (d3 >> 1)) & 3)];
                    a0.x += v0.x; a0.y += v0.y; a0.z += v0.z; a0.w += v0.w;
                    a1.x += v1.x; a1.y += v1.y; a1.z += v1.z; a1.w += v1.w;
                    a2.x += v2.x; a2.y += v2.y; a2.z += v2.z; a2.w += v2.w;
                    a3.x += v3.x; a3.y += v3.y; a3.z += v3.z; a3.w += v3.w;
                }
            }

            // stage group g+1 (already in nv) into the other buffer
            if (g + 1 < ngr) {
                int gs1 = min(4, nt - ((g + 1) << 2));
                float4* dbuf = s_r + (size_t)((g + 1) & 1) * 4096;
                if (0 < gs1) dbuf[0 * 1024 + swst] = nv0;
                if (1 < gs1) dbuf[1 * 1024 + swst] = nv1;
                if (2 < gs1) dbuf[2 * 1024 + swst] = nv2;
                if (3 < gs1) dbuf[3 * 1024 + swst] = nv3;
            }
            // prefetch group g+2
            if (g + 2 < ngr) {
                int gb2 = (g + 2) << 2;
                int gs2 = min(4, nt - gb2);
                const float4* rs =
                    (const float4*)resp + (size_t)(t0 + gb2) * 1024 + tid;
                if (0 < gs2) nv0 = rs[0];
                if (1 < gs2) nv1 = rs[1024];
                if (2 < gs2) nv2 = rs[2048];
                if (3 < gs2) nv3 = rs[3072];
            }
            __syncthreads();
        }

        // flush this segment's partials (slot = 2*block + segment)
        int slot = i * 2 + ph;
        float4* pb = (float4*)g_part + ((size_t)slot * 1024 + sbase) * 4 + q;
        pb[0] = a0; pb[4] = a1; pb[8] = a2; pb[12] = a3;

        ph++;
        u = segend;
    }
}

// ---------------- kernel 4: reduce mapped partial slots ----------------------
__global__ __launch_bounds__(256) void k_reduce(float* __restrict__ out) {
    int idx = blockIdx.x * 256 + threadIdx.x;   // float2 id, 131072 total
    int b   = idx >> 3;                         // sample 0..16383
    int c2  = idx & 7;                          // float2 within 16 floats
    int bt  = b >> 10, s = b & 1023;

    int i = (37 * bt) >> 2;                     // ~ first contributing block
    while (U0(i + 1) <= (bt << 8)) i++;
    while (i > 0 && U0(i) > (bt << 8)) i--;

    float sx = 0.f, sy = 0.f;
    for (; i < NBLK && U0(i) < ((bt + 1) << 8); i++) {
        int ph   = ((U0(i) >> 8) == bt) ? 0 : 1;
        int slot = i * 2 + ph;
        const float2* p =
            (const float2*)g_part + ((size_t)slot * 1024 + s) * 8 + c2;
        float2 v = *p;
        sx += v.x; sy += v.y;
    }
    const float sc = 1.0f / (float)Tn;
    ((float2*)out)[(size_t)b * 8 + c2] = make_float2(sx * sc, sy * sc);
}

// ---------------- launch -----------------------------------------------------
extern "C" void kernel_launch(void* const* d_in, const int* in_sizes, int n_in,
                              void* d_out, int out_size) {
    const float* x    = (const float*)d_in[0];   // (B, F)
    const float* fw   = (const float*)d_in[1];   // (T, D, F)
    const float* thr  = (const float*)d_in[2];   // (T, D)
    const float* resp = (const float*)d_in[3];   // (T, L, C)
    float* out = (float*)d_out;                  // (B, C)

    const int smem_dec = 32 * 513 * 4 + Tn * 16 + Tn * Dn * 4;   // 77952 B
    const int smem_acc = 8192 * 16 + 28 * 256 * 4;               // 159744 B
    cudaFuncSetAttribute(k_decide, cudaFuncAttributeMaxDynamicSharedMemorySize,
                         smem_dec);
    cudaFuncSetAttribute(k_accum, cudaFuncAttributeMaxDynamicSharedMemorySize,
                         smem_acc);
    (void)in_sizes; (void)n_in; (void)out_size;

    k_argmax<<<(Tn * Dn) / 8, 256>>>(fw);                 // launch 1
    k_decide<<<Bn / 32, 512, smem_dec>>>(x, thr);         // launch 2
    k_tiny<<<1, 32>>>();                                  // launch 3 (shim)
    k_accum<<<NBLK, 1024, smem_acc>>>(resp);              // launch 4 <- ncu
    k_reduce<<<(Bn * Cn / 2) / 256, 256>>>(out);          // launch 5
}

// round 16
// speedup vs baseline: 1.1001x; 1.1001x over previous
#include <cuda_runtime.h>
#include <stdint.h>

#define Bn 16384
#define Tn 256
#define Dn 8
#define Fn 512
#define Cn 16
#define Ln 256

#define NBLK 148             // persistent accum blocks, 1 per SM, 1 slot each
#define DUMMY 148            // zeroed dummy partial slot

// ---------------- device scratch (static, no runtime allocation) ------------
__device__ unsigned short g_fidx16[Tn * Dn];   // PRE-SCALED byte offsets
__device__ unsigned char  g_dec[(size_t)Tn * Bn];             // 4 MB [T][B]
__device__ float          g_part[(size_t)(NBLK + 1) * 1024 * Cn]; // 9.8 MB
__device__ int            g_scratch[16];

// block i -> (btile, tree range): btiles 0-3 have 10 chunks, 4-15 have 9.
__device__ __forceinline__ void block_map(int i, int& bt, int& t0, int& t1) {
    if (i < 40) { bt = i / 10; int c = i % 10;
                  t0 = (c * 256) / 10; t1 = ((c + 1) * 256) / 10; }
    else        { int j = i - 40; bt = 4 + j / 9; int c = j % 9;
                  t0 = (c * 256) / 9;  t1 = ((c + 1) * 256) / 9; }
}

// ---------------- kernel 1: argmax over F per (tree, depth) -----------------
__global__ void k_argmax(const float* __restrict__ fw) {
    // blocks 0-15 also zero the dummy partial slot (64 KB)
    if (blockIdx.x < 16) {
        float4* z = (float4*)g_part + (size_t)DUMMY * 1024 * 4
                  + blockIdx.x * 256 + threadIdx.x;
        *z = make_float4(0.f, 0.f, 0.f, 0.f);
    }

    int g    = blockIdx.x * 8 + (threadIdx.x >> 5);   // 2048 warps total
    int lane = threadIdx.x & 31;
    const float* p = fw + (size_t)g * Fn;

    float v[16];
    #pragma unroll
    for (int i = 0; i < 16; i++) v[i] = p[lane + (i << 5)];

    float best = v[0];
    int   bi   = lane;
    #pragma unroll
    for (int i = 1; i < 16; i++)
        if (v[i] > best) { best = v[i]; bi = lane + (i << 5); }

    #pragma unroll
    for (int off = 16; off; off >>= 1) {
        float ov = __shfl_down_sync(0xffffffffu, best, off);
        int   oi = __shfl_down_sync(0xffffffffu, bi,   off);
        if (ov > best || (ov == best && oi < bi)) { best = ov; bi = oi; }
    }
    if (lane == 0)
        g_fidx16[g] = (unsigned short)((((bi & 3) << 7) + (bi >> 2)) << 2);
}

// ---------------- kernel 2: per-(sample,tree) decision byte -----------------
// (round-13 version — best measured; LSU-floor-bound, closed)
__global__ __launch_bounds__(512) void k_decide(const float* __restrict__ x,
                                                const float* __restrict__ thr) {
    extern __shared__ float smem[];
    float* s_x   = smem;                                   // 32 * 513 floats
    uint4* s_fpk = (uint4*)(smem + 32 * 513);              // 256 * 16 B
    float* s_thr = (float*)(s_fpk + Tn);                   // 2048 floats

    int tid = threadIdx.x;
    int b0  = blockIdx.x * 32;

    const float4* xg = (const float4*)x + (size_t)b0 * (Fn / 4);
    for (int i = tid; i < 32 * (Fn / 4); i += 512) {
        float4 v = xg[i];
        int row = i >> 7, c4 = i & 127;
        float* dst = s_x + row * 513 + c4;
        dst[0]   = v.x;
        dst[128] = v.y;
        dst[256] = v.z;
        dst[384] = v.w;
    }
    for (int i = tid; i < (Tn * Dn) / 2; i += 512)
        ((unsigned*)s_fpk)[i] = ((const unsigned*)g_fidx16)[i];
    for (int i = tid; i < Tn * Dn; i += 512)
        s_thr[i] = thr[i];
    __syncthreads();

    int warp = tid >> 5, lane = tid & 31;
    const char* xr = (const char*)(s_x + lane * 513);

    #pragma unroll 4
    for (int tt = 0; tt < 16; tt++) {
        int t = warp * 16 + tt;
        uint4 fp = s_fpk[t];
        const float4* th = (const float4*)(s_thr + t * 8);
        float4 t0 = th[0], t1 = th[1];
        float x0 = *(const float*)(xr + (fp.x & 0xFFFFu));
        float x1 = *(const float*)(xr + (fp.x >> 16));
        float x2 = *(const float*)(xr + (fp.y & 0xFFFFu));
        float x3 = *(const float*)(xr + (fp.y >> 16));
        float x4 = *(const float*)(xr + (fp.z & 0xFFFFu));
        float x5 = *(const float*)(xr + (fp.z >> 16));
        float x6 = *(const float*)(xr + (fp.w & 0xFFFFu));
        float x7 = *(const float*)(xr + (fp.w >> 16));
        unsigned s0 = __float_as_uint(t0.x - x0) >> 31;
        unsigned s1 = __float_as_uint(t0.y - x1) >> 31;
        unsigned s2 = __float_as_uint(t0.z - x2) >> 31;
        unsigned s3 = __float_as_uint(t0.w - x3) >> 31;
        unsigned s4 = __float_as_uint(t1.x - x4) >> 31;
        unsigned s5 = __float_as_uint(t1.y - x5) >> 31;
        unsigned s6 = __float_as_uint(t1.z - x6) >> 31;
        unsigned s7 = __float_as_uint(t1.w - x7) >> 31;
        unsigned dec = (s0 << 7) | (s1 << 6) | (s2 << 5) | (s3 << 4) |
                       (s4 << 3) | (s5 << 2) | (s6 << 1) | s7;
        g_dec[(size_t)t * Bn + b0 + lane] = (unsigned char)dec;
    }
}

// ---------------- launch-slot shim (keeps k_accum in the ncu slot) ----------
__global__ void k_tiny() { if (threadIdx.x < 16) g_scratch[threadIdx.x] = 0; }

// ---------------- kernel 3: persistent gather, REPLICATED rows ---------------
// 148 blocks x 1024 threads (1/SM); block i owns one (btile, tree-chunk).
// Leaf row d stored TWICE: addr(d,p,q) = d*8 + p*4 + q (one replica per
// bank-half). Gather phase = sample-groups {sg, sg+1} x 4 quarters; with
// p = sg&1 the two rows of every phase live in disjoint halves ->
// CONFLICT-FREE gathers (cost 1/phase, was E=1.5). Staging stores both
// replicas; halves alternate with d parity -> staging also conflict-free.
// dec table staged once per block; response double-buffered, distance-2
// register prefetch (round-14 structure, best measured).
__global__ __launch_bounds__(1024) void k_accum(const float* __restrict__ resp) {
    extern __shared__ float4 dynsmem[];
    float4*   s_r    = dynsmem;                        // 2 * 2048 float4 = 64 KB
    unsigned* s_dall = (unsigned*)(dynsmem + 4096);    // up to 29*256 u32

    int i   = blockIdx.x;
    int tid = threadIdx.x;
    int w   = tid >> 5;
    int l   = tid & 31;
    int q   = l & 3;
    int sg  = l >> 2;
    int sbase = w * 32 + sg * 4;           // first of this thread's 4 samples
    int dword = w * 8 + sg;                // dec word index for this thread
    int p4q   = ((sg & 1) << 2) + q;       // replica half + quarter offset

    int bt, t0g, t1g;
    block_map(i, bt, t0g, t1g);
    int nt = t1g - t0g;                    // 25..29 trees
    int b0 = bt << 10;

    // staging slots for this thread's float4 (d = tid>>2, k = tid&3)
    int d_st = tid >> 2, k_st = tid & 3;
    int sw0 = d_st * 8 + ((d_st & 1) << 2) + k_st;        // replica in half d&1
    int sw1 = d_st * 8 + ((1 - (d_st & 1)) << 2) + k_st;  // other half

    // stage ALL dec words for this block's chunk
    for (int j = tid; j < nt * 256; j += 1024) {
        int tt = j >> 8, wd = j & 255;
        s_dall[j] =
            *((const unsigned*)(g_dec + (size_t)(t0g + tt) * Bn + b0) + wd);
    }

    float4 a0 = make_float4(0.f, 0.f, 0.f, 0.f);
    float4 a1 = a0, a2 = a0, a3 = a0;
    float4 nv;

    // prologue: tree t0g -> buf0 (both replicas), prefetch t0g+1 -> nv
    {
        const float4* rs = (const float4*)resp + (size_t)t0g * 1024;
        nv = rs[tid];
        s_r[sw0] = nv;
        s_r[sw1] = nv;
        if (nt > 1) {
            const float4* rs1 = (const float4*)resp + (size_t)(t0g + 1) * 1024;
            nv = rs1[tid];
        }
    }
    __syncthreads();

    for (int tt = 0; tt < nt; tt++) {
        const float4* srb = s_r + (tt & 1) * 2048 + p4q;
        unsigned dw = s_dall[tt * 256 + dword];
        int d0 = dw & 255, d1 = (dw >> 8) & 255;
        int d2 = (dw >> 16) & 255, d3 = dw >> 24;
        float4 v0 = srb[d0 * 8];
        float4 v1 = srb[d1 * 8];
        float4 v2 = srb[d2 * 8];
        float4 v3 = srb[d3 * 8];
        a0.x += v0.x; a0.y += v0.y; a0.z += v0.z; a0.w += v0.w;
        a1.x += v1.x; a1.y += v1.y; a1.z += v1.z; a1.w += v1.w;
        a2.x += v2.x; a2.y += v2.y; a2.z += v2.z; a2.w += v2.w;
        a3.x += v3.x; a3.y += v3.y; a3.z += v3.z; a3.w += v3.w;

        if (tt + 1 < nt) {                 // stage tree tt+1 (in nv)
            float4* dbuf = s_r + ((tt + 1) & 1) * 2048;
            dbuf[sw0] = nv;
            dbuf[sw1] = nv;
        }
        if (tt + 2 < nt) {                 // prefetch tree tt+2
            const float4* rs =
                (const float4*)resp + (size_t)(t0g + tt + 2) * 1024;
            nv = rs[tid];
        }
        __syncthreads();
    }

    // flush partials: slot = block index (one slot per block)
    float4* pb = (float4*)g_part + ((size_t)i * 1024 + sbase) * 4 + q;
    pb[0] = a0; pb[4] = a1; pb[8] = a2; pb[12] = a3;
}

// ---------------- kernel 4: reduce fixed-10 mapped slots ---------------------
// btile bt reads slots [base, base+n) (n = 10 or 9) + dummy padding; fully
// unrolled, 10 independent loads per thread.
__global__ __launch_bounds__(256) void k_reduce(float* __restrict__ out) {
    int idx = blockIdx.x * 256 + threadIdx.x;   // float2 id, 131072 total
    int b   = idx >> 3;                         // sample 0..16383
    int c2  = idx & 7;                          // float2 within 16 floats
    int bt  = b >> 10, s = b & 1023;

    int base, n;
    if (bt < 4) { base = bt * 10;           n = 10; }
    else        { base = 40 + (bt - 4) * 9; n = 9;  }

    float sx = 0.f, sy = 0.f;
    #pragma unroll
    for (int j = 0; j < 10; j++) {
        int slot = (j < n) ? (base + j) : DUMMY;
        const float2* p =
            (const float2*)g_part + ((size_t)slot * 1024 + s) * 8 + c2;
        float2 v = *p;
        sx += v.x; sy += v.y;
    }
    const float sc = 1.0f / (float)Tn;
    ((float2*)out)[(size_t)b * 8 + c2] = make_float2(sx * sc, sy * sc);
}

// ---------------- launch -----------------------------------------------------
extern "C" void kernel_launch(void* const* d_in, const int* in_sizes, int n_in,
                              void* d_out, int out_size) {
    const float* x    = (const float*)d_in[0];   // (B, F)
    const float* fw   = (const float*)d_in[1];   // (T, D, F)
    const float* thr  = (const float*)d_in[2];   // (T, D)
    const float* resp = (const float*)d_in[3];   // (T, L, C)
    float* out = (float*)d_out;                  // (B, C)

    const int smem_dec = 32 * 513 * 4 + Tn * 16 + Tn * Dn * 4;   // 77952 B
    const int smem_acc = 4096 * 16 + 29 * 256 * 4;               // 95232 B
    cudaFuncSetAttribute(k_decide, cudaFuncAttributeMaxDynamicSharedMemorySize,
                         smem_dec);
    cudaFuncSetAttribute(k_accum, cudaFuncAttributeMaxDynamicSharedMemorySize,
                         smem_acc);
    (void)in_sizes; (void)n_in; (void)out_size;

    k_argmax<<<(Tn * Dn) / 8, 256>>>(fw);                 // launch 1
    k_decide<<<Bn / 32, 512, smem_dec>>>(x, thr);         // launch 2
    k_tiny<<<1, 32>>>();                                  // launch 3 (shim)
    k_accum<<<NBLK, 1024, smem_acc>>>(resp);              // launch 4 <- ncu
    k_reduce<<<(Bn * Cn / 2) / 256, 256>>>(out);          // launch 5
}